// round 10
// baseline (speedup 1.0000x reference)
#include <cuda_runtime.h>

// Problem: B=2, C=32, H=80, W=240, D=64 (MAXDISP=192, D=192/3)
// out shape (B, 2C, D, H, W) fp32:
//   left  (c2 <  32): out = x[b,c2,h,w]        * (w >= d)
//   right (c2 >= 32): out = y[b,c2-32,h,w-d]   * (w >= d)
//
// 629 MB of stores, ~10 MB of (heavily reused) loads. Pure store-BW bound.
// Cache-op sweep at the 4-float4/thread configuration:
//   __stcs : 94.4 us  (R8)
//   __stwt : 99.0 us  (R9, regression — no L2 bypass, lost write-combining)
//   plain  : this round (default write-back; inputs are 10 MB vs 126 MB L2,
//            single-pass write stream should not evict them meaningfully)
// Everything else identical to R8.

#define BN 2
#define CN 32
#define HN 80
#define WN 240
#define DN 64
#define W4 (WN / 4)                               // 60 float4 per row
#define TOTAL4 (BN * 2 * CN * DN * HN * W4)       // 39,321,600 = 38400 * 1024

__device__ __forceinline__ float4 compute_elem(
    const float* __restrict__ x, const float* __restrict__ y, unsigned int i)
{
    // i -> (row, w4); row -> (b, c2, d, h), h fastest
    unsigned int row = i / W4;                    // magic-number div
    unsigned int w4  = i - row * W4;
    unsigned int h   = row % HN;                  // magic-number mod
    unsigned int t   = row / HN;
    unsigned int d   = t & (DN - 1);   t >>= 6;
    unsigned int c2  = t & (2 * CN - 1);
    unsigned int b   = t >> 6;

    int w0 = (int)(w4 * 4);
    int di = (int)d;
    float4 v;

    if (c2 < CN) {
        // left: aligned float4 load from x, mask lanes where w < d
        const float4* xr = reinterpret_cast<const float4*>(
            x + (((b * CN + c2) * HN + h) * WN));
        v = __ldg(xr + w4);
        if (w0 < di) {
            v.x = (w0     >= di) ? v.x : 0.0f;
            v.y = (w0 + 1 >= di) ? v.y : 0.0f;
            v.z = (w0 + 2 >= di) ? v.z : 0.0f;
            v.w = (w0 + 3 >= di) ? v.w : 0.0f;
        }
    } else {
        // right: y[b, c, h, w - d]; scalar loads (misaligned by d), y is
        // L2-resident (4.9 MB, 64x reuse) so latency is hidden.
        unsigned int c = c2 - CN;
        const float* yr = y + (((b * CN + c) * HN + h) * WN);
        v.x = (w0     >= di) ? __ldg(yr + (w0     - di)) : 0.0f;
        v.y = (w0 + 1 >= di) ? __ldg(yr + (w0 + 1 - di)) : 0.0f;
        v.z = (w0 + 2 >= di) ? __ldg(yr + (w0 + 2 - di)) : 0.0f;
        v.w = (w0 + 3 >= di) ? __ldg(yr + (w0 + 3 - di)) : 0.0f;
    }
    return v;
}

__global__ __launch_bounds__(256)
void cost_volume_kernel(const float* __restrict__ x,
                        const float* __restrict__ y,
                        float* __restrict__ out)
{
    unsigned int j0 = blockIdx.x * 1024u + threadIdx.x;

    float4 v0 = compute_elem(x, y, j0);
    float4 v1 = compute_elem(x, y, j0 + 256u);
    float4 v2 = compute_elem(x, y, j0 + 512u);
    float4 v3 = compute_elem(x, y, j0 + 768u);

    float4* o = reinterpret_cast<float4*>(out);
    o[j0]        = v0;                            // default st.global (write-back)
    o[j0 + 256u] = v1;
    o[j0 + 512u] = v2;
    o[j0 + 768u] = v3;
}

extern "C" void kernel_launch(void* const* d_in, const int* in_sizes, int n_in,
                              void* d_out, int out_size)
{
    const float* x = (const float*)d_in[0];
    const float* y = (const float*)d_in[1];
    float* out = (float*)d_out;

    cost_volume_kernel<<<TOTAL4 / 1024, 256>>>(x, y, out);
}

// round 11
// speedup vs baseline: 1.1169x; 1.1169x over previous
#include <cuda_runtime.h>

// Problem: B=2, C=32, H=80, W=240, D=64 (MAXDISP=192, D=192/3)
// out shape (B, 2C, D, H, W) fp32:
//   left  (c2 <  32): out = x[b,c2,h,w]        * (w >= d)
//   right (c2 >= 32): out = y[b,c2-32,h,w-d]   * (w >= d)
//
// 629 MB of stores, ~10 MB of L2-resident loads. Store-BW bound.
// Cache-op sweep: __stcs 94.4us / __stwt 99.0 / plain 100.3 -> __stcs.
//
// Structural trick this round: with Q = TOTAL4/4 = 32*64*80*60, the output
// float4s j, j+Q, j+2Q, j+3Q are exactly {b0-left, b0-right, b1-left,
// b1-right} of the SAME (c, d, h, w4). Each thread decomposes its index
// ONCE (c = t>>6 is automatically < 32 since j < Q), computes the w>=d
// mask once, and emits all four 128-bit streaming stores. No branches at
// all -> zero divergence; ~3/4 of the per-thread integer work removed.

#define W4N   60
#define QCNT  9830400u          // 32*64*80*60  (c2+32 stride in float4s)
#define PLANE 614400u           // 32*80*240    (per-batch input floats)

__global__ __launch_bounds__(256)
void cost_volume_kernel(const float* __restrict__ x,
                        const float* __restrict__ y,
                        float* __restrict__ out)
{
    unsigned int j0 = blockIdx.x * 256u + threadIdx.x;   // j0 in [0, QCNT)

    // Single decomposition: j0 -> (c, d, h, w4)
    unsigned int row = j0 / W4N;                 // magic-number div
    unsigned int w4  = j0 - row * W4N;
    unsigned int h   = row % 80u;                // magic-number mod
    unsigned int t   = row / 80u;                // t < 2048
    unsigned int d   = t & 63u;
    unsigned int c   = t >> 6;                   // < 32 by construction

    int w0 = (int)(w4 * 4u);
    int di = (int)d;
    bool m0 = (w0     >= di);
    bool m1 = (w0 + 1 >= di);
    bool m2 = (w0 + 2 >= di);
    bool m3 = (w0 + 3 >= di);

    unsigned int off = (c * 80u + h) * 240u;     // b=0 row base (floats), %4==0

    // left halves: aligned float4 loads from x, lane-masked
    const float4* x4 = reinterpret_cast<const float4*>(x);
    float4 vL0 = __ldg(x4 + (off >> 2) + w4);
    float4 vL1 = __ldg(x4 + ((off + PLANE) >> 2) + w4);
    if (!m0) { vL0.x = 0.0f; vL1.x = 0.0f; }
    if (!m1) { vL0.y = 0.0f; vL1.y = 0.0f; }
    if (!m2) { vL0.z = 0.0f; vL1.z = 0.0f; }
    if (!m3) { vL0.w = 0.0f; vL1.w = 0.0f; }

    // right halves: y shifted by d; scalar loads (L2-resident, 64x reuse)
    const float* yr0 = y + off;
    const float* yr1 = yr0 + PLANE;
    float4 vR0, vR1;
    vR0.x = m0 ? __ldg(yr0 + (w0     - di)) : 0.0f;
    vR0.y = m1 ? __ldg(yr0 + (w0 + 1 - di)) : 0.0f;
    vR0.z = m2 ? __ldg(yr0 + (w0 + 2 - di)) : 0.0f;
    vR0.w = m3 ? __ldg(yr0 + (w0 + 3 - di)) : 0.0f;
    vR1.x = m0 ? __ldg(yr1 + (w0     - di)) : 0.0f;
    vR1.y = m1 ? __ldg(yr1 + (w0 + 1 - di)) : 0.0f;
    vR1.z = m2 ? __ldg(yr1 + (w0 + 2 - di)) : 0.0f;
    vR1.w = m3 ? __ldg(yr1 + (w0 + 3 - di)) : 0.0f;

    // Four perfectly-coalesced streaming store streams, QCNT apart.
    float4* o = reinterpret_cast<float4*>(out);
    __stcs(o + j0,             vL0);   // b=0, left  (c2 = c)
    __stcs(o + j0 + QCNT,      vR0);   // b=0, right (c2 = c+32)
    __stcs(o + j0 + 2u * QCNT, vL1);   // b=1, left
    __stcs(o + j0 + 3u * QCNT, vR1);   // b=1, right
}

extern "C" void kernel_launch(void* const* d_in, const int* in_sizes, int n_in,
                              void* d_out, int out_size)
{
    const float* x = (const float*)d_in[0];
    const float* y = (const float*)d_in[1];
    float* out = (float*)d_out;

    cost_volume_kernel<<<QCNT / 256, 256>>>(x, y, out);   // 38,400 blocks
}

// round 13
// speedup vs baseline: 1.1376x; 1.0185x over previous
#include <cuda_runtime.h>

// B=2, C=32, H=80, W=240, D=64. out (B, 2C, D, H, W) fp32.
// 629 MB stores, ~10 MB L2-resident loads. Store-BW bound.
// R11 = 89.8us (7.0 TB/s): shared decomposition, 4 __stcs streams/thread.
// Profile: DRAM 77.5%, L1 76.0% co-binding. The 8 scalar y LDG.32s (16B
// lane stride) were 32/56 L1 wavefronts/warp at 25% sector utilization.
//
// This round: replace them with aligned float4 pairs (A=y4[q], B=y4[q+1])
// + select on r=(w0-d)&3. 32 wf -> 16 wf on the y path; all edge cases
// (q<=-2 fully masked, q=-1 valid lanes only in B=y4[0], r=0 aliases B=A
// to avoid reading past the last row) are mask-safe.

#define W4N   60
#define QCNT  9830400u          // 32*64*80*60  (c2+32 stride in float4s)
#define PLANE 614400u           // 32*80*240    (per-batch input floats)

__device__ __forceinline__ float sel4(float4 a, int p) {
    return p == 0 ? a.x : p == 1 ? a.y : p == 2 ? a.z : a.w;
}

// floats at positions r..r+3 of the 8-float window [A, B]
__device__ __forceinline__ float4 shift_sel(float4 A, float4 B, int r) {
    float4 v;
    v.x = sel4(A, r);
    v.y = (r < 3) ? sel4(A, r + 1) : B.x;
    v.z = (r < 2) ? sel4(A, r + 2) : sel4(B, r - 2);
    v.w = (r < 1) ? A.w : sel4(B, r - 1);
    return v;
}

__global__ __launch_bounds__(256)
void cost_volume_kernel(const float* __restrict__ x,
                        const float* __restrict__ y,
                        float* __restrict__ out)
{
    unsigned int j0 = blockIdx.x * 256u + threadIdx.x;   // j0 in [0, QCNT)

    // Single decomposition: j0 -> (c, d, h, w4)
    unsigned int row = j0 / W4N;
    unsigned int w4  = j0 - row * W4N;
    unsigned int h   = row % 80u;
    unsigned int t   = row / 80u;                // t < 2048
    unsigned int d   = t & 63u;
    unsigned int c   = t >> 6;                   // < 32 by construction

    int w0 = (int)(w4 * 4u);
    int di = (int)d;
    bool m0 = (w0     >= di);
    bool m1 = (w0 + 1 >= di);
    bool m2 = (w0 + 2 >= di);
    bool m3 = (w0 + 3 >= di);

    unsigned int off  = (c * 80u + h) * 240u;    // b=0 row base (floats), %4==0
    unsigned int rb0  = off >> 2;                // row base in float4s
    unsigned int rb1  = (off + PLANE) >> 2;

    // ── left halves: aligned float4 loads from x, lane-masked ──
    const float4* x4 = reinterpret_cast<const float4*>(x);
    float4 vL0 = __ldg(x4 + rb0 + w4);
    float4 vL1 = __ldg(x4 + rb1 + w4);
    if (!m0) { vL0.x = 0.0f; vL1.x = 0.0f; }
    if (!m1) { vL0.y = 0.0f; vL1.y = 0.0f; }
    if (!m2) { vL0.z = 0.0f; vL1.z = 0.0f; }
    if (!m3) { vL0.w = 0.0f; vL1.w = 0.0f; }

    // ── right halves: misaligned y window via aligned float4 pair + select ──
    int s  = w0 - di;                 // -63 .. 236
    int q  = s >> 2;                  // floor div (arithmetic shift)
    int r  = s & 3;
    int qa = max(q, 0);
    int qb = (r == 0) ? qa : max(q + 1, 0);   // r==0: all picks from A; no OOB

    const float4* y4 = reinterpret_cast<const float4*>(y);
    float4 A0 = __ldg(y4 + rb0 + qa);
    float4 B0 = __ldg(y4 + rb0 + qb);
    float4 A1 = __ldg(y4 + rb1 + qa);
    float4 B1 = __ldg(y4 + rb1 + qb);

    float4 vR0 = shift_sel(A0, B0, r);
    float4 vR1 = shift_sel(A1, B1, r);
    if (!m0) { vR0.x = 0.0f; vR1.x = 0.0f; }
    if (!m1) { vR0.y = 0.0f; vR1.y = 0.0f; }
    if (!m2) { vR0.z = 0.0f; vR1.z = 0.0f; }
    if (!m3) { vR0.w = 0.0f; vR1.w = 0.0f; }

    // ── four perfectly-coalesced streaming store streams, QCNT apart ──
    float4* o = reinterpret_cast<float4*>(out);
    __stcs(o + j0,             vL0);   // b=0, left  (c2 = c)
    __stcs(o + j0 + QCNT,      vR0);   // b=0, right (c2 = c+32)
    __stcs(o + j0 + 2u * QCNT, vL1);   // b=1, left
    __stcs(o + j0 + 3u * QCNT, vR1);   // b=1, right
}

extern "C" void kernel_launch(void* const* d_in, const int* in_sizes, int n_in,
                              void* d_out, int out_size)
{
    const float* x = (const float*)d_in[0];
    const float* y = (const float*)d_in[1];
    float* out = (float*)d_out;

    cost_volume_kernel<<<QCNT / 256, 256>>>(x, y, out);   // 38,400 blocks
}